// round 5
// baseline (speedup 1.0000x reference)
#include <cuda_runtime.h>
#include <math.h>
#include <stdint.h>

// ---------------------------------------------------------------------------
// Problem constants
// ---------------------------------------------------------------------------
#define EPSLN 1e-5f
#define DT    0.01f
#define CDIM  256
#define BDIM  8
#define NTOK  256
#define HEADS 8
#define HD    32
#define ROWS  (BDIM * NTOK)   // 2048

// ODE tiling
#define MROW 16          // rows per CTA
#define MP   20          // padded row-stride (floats) in transposed smem buffers
#define MPB  (MP * 4)    // 80 bytes
#define KB   32          // k-block size for weight staging
#define WBYTES (KB * CDIM * 4)   // 32 KB per weight block

// smem byte offsets for ODE kernel
#define OFF_YS   0
#define OFF_K1   20480
#define OFF_K2   40960
#define OFF_K3   61440
#define OFF_ARGS 81920
#define OFF_H1   102400
#define OFF_W0   122880
#define OFF_W1   155648
#define OFF_W2   188416
#define OFF_RED  221184
#define ODE_SMEM 221696

typedef unsigned long long U64;

// ---------------------------------------------------------------------------
// Scratch (device globals: no allocation allowed)
// ---------------------------------------------------------------------------
__device__ float g_qbuf[3 * BDIM * HEADS * NTOK * HD]; // [3][B][H][N][hd]
__device__ float g_attnout[ROWS * CDIM];               // attention concat [B*N][C]
__device__ float g_x1[ROWS * CDIM];                    // x1 = LN(x + attn)
__device__ float g_ode[ROWS * CDIM];                   // ODE output at lead time

// ---------------------------------------------------------------------------
// packed f32x2 helpers (Blackwell FFMA2 path)
// ---------------------------------------------------------------------------
__device__ __forceinline__ U64 pack2(float lo, float hi) {
    U64 r; asm("mov.b64 %0, {%1, %2};" : "=l"(r) : "f"(lo), "f"(hi)); return r;
}
__device__ __forceinline__ void unpack2(U64 v, float& lo, float& hi) {
    asm("mov.b64 {%0, %1}, %2;" : "=f"(lo), "=f"(hi) : "l"(v));
}
__device__ __forceinline__ U64 fma2(U64 a, U64 b, U64 c) {
    U64 d; asm("fma.rn.f32x2 %0, %1, %2, %3;" : "=l"(d) : "l"(a), "l"(b), "l"(c)); return d;
}
__device__ __forceinline__ U64 add2(U64 a, U64 b) {
    U64 d; asm("add.rn.f32x2 %0, %1, %2;" : "=l"(d) : "l"(a), "l"(b)); return d;
}
__device__ __forceinline__ U64 mul2(U64 a, U64 b) {
    U64 d; asm("mul.rn.f32x2 %0, %1, %2;" : "=l"(d) : "l"(a), "l"(b)); return d;
}
__device__ __forceinline__ void lds2x64(uint32_t addr, U64& a, U64& b) {
    asm volatile("ld.shared.v2.b64 {%0, %1}, [%2];" : "=l"(a), "=l"(b) : "r"(addr));
}
__device__ __forceinline__ void lds2f(uint32_t addr, float& a, float& b) {
    asm volatile("ld.shared.v2.f32 {%0, %1}, [%2];" : "=f"(a), "=f"(b) : "r"(addr));
}
__device__ __forceinline__ void lds4f(uint32_t addr, float& x, float& y, float& z, float& w) {
    asm volatile("ld.shared.v4.f32 {%0, %1, %2, %3}, [%4];"
                 : "=f"(x), "=f"(y), "=f"(z), "=f"(w) : "r"(addr));
}
__device__ __forceinline__ void sts2x64(uint32_t addr, U64 a, U64 b) {
    asm volatile("st.shared.v2.b64 [%0], {%1, %2};" :: "r"(addr), "l"(a), "l"(b));
}
__device__ __forceinline__ void sts4f(uint32_t addr, float x, float y, float z, float w) {
    asm volatile("st.shared.v4.f32 [%0], {%1, %2, %3, %4};"
                 :: "r"(addr), "f"(x), "f"(y), "f"(z), "f"(w));
}
__device__ __forceinline__ void cp_async16(uint32_t sdst, const void* gsrc) {
    asm volatile("cp.async.cg.shared.global [%0], [%1], 16;" :: "r"(sdst), "l"(gsrc));
}
__device__ __forceinline__ void cp_commit() { asm volatile("cp.async.commit_group;"); }
__device__ __forceinline__ void cp_wait1() { asm volatile("cp.async.wait_group 1;" ::: "memory"); }
__device__ __forceinline__ void cp_wait_all() { asm volatile("cp.async.wait_group 0;" ::: "memory"); }

// ---------------------------------------------------------------------------
// K1: qkv = x @ wqkv + bqkv, scattered into [3][B][H][N][hd]
// ---------------------------------------------------------------------------
__global__ void qkv_kernel(const float* __restrict__ x,
                           const float* __restrict__ wqkv,
                           const float* __restrict__ bqkv) {
    __shared__ __align__(16) float As[CDIM * 36];
    int tid = threadIdx.x, cg = tid & 31, rg = tid >> 5;
    int r0 = blockIdx.x * 32;
    int cb = blockIdx.y;

    for (int idx = tid; idx < 32 * CDIM; idx += 256) {
        int c = idx & 255, m = idx >> 8;
        As[c * 36 + m] = x[(r0 + m) * CDIM + c];
    }
    __syncthreads();

    float acc[4][8];
#pragma unroll
    for (int j = 0; j < 8; j++) {
        float bv = bqkv[cb * 256 + cg + 32 * j];
#pragma unroll
        for (int mm = 0; mm < 4; mm++) acc[mm][j] = bv;
    }
    int m0 = rg * 4;
    const float* wp = wqkv + cb * 256 + cg;
#pragma unroll 4
    for (int k = 0; k < CDIM; k++) {
        float4 av = *(const float4*)(As + k * 36 + m0);
#pragma unroll
        for (int j = 0; j < 8; j++) {
            float w = wp[k * 768 + 32 * j];
            acc[0][j] = fmaf(av.x, w, acc[0][j]);
            acc[1][j] = fmaf(av.y, w, acc[1][j]);
            acc[2][j] = fmaf(av.z, w, acc[2][j]);
            acc[3][j] = fmaf(av.w, w, acc[3][j]);
        }
    }
#pragma unroll
    for (int mm = 0; mm < 4; mm++) {
        int r = r0 + m0 + mm;
        int b = r >> 8, n = r & 255;
#pragma unroll
        for (int j = 0; j < 8; j++) {
            int cl = cg + 32 * j;
            int h = cl >> 5, d = cl & 31;
            g_qbuf[(((cb * BDIM + b) * HEADS + h) * NTOK + n) * HD + d] = acc[mm][j];
        }
    }
}

// ---------------------------------------------------------------------------
// K2: per-(b,h) softmax attention
// ---------------------------------------------------------------------------
#define ATTN_SMEM ((3 * 256 * 33 + 8 * 256) * 4)

__global__ void attn_kernel() {
    extern __shared__ float sm[];
    float* qs = sm;
    float* ks = qs + 256 * 33;
    float* vs = ks + 256 * 33;
    float* prob = vs + 256 * 33;

    int tid = threadIdx.x, lane = tid & 31, w = tid >> 5;
    int bh = blockIdx.x, b = bh >> 3, h = bh & 7;
    const float scale = 0.17677669529663687f;

    const float* qg = g_qbuf + ((0 * BDIM + b) * HEADS + h) * NTOK * HD;
    const float* kg = g_qbuf + ((1 * BDIM + b) * HEADS + h) * NTOK * HD;
    const float* vg = g_qbuf + ((2 * BDIM + b) * HEADS + h) * NTOK * HD;
    for (int idx = tid; idx < NTOK * HD; idx += 256) {
        int n = idx >> 5, d = idx & 31;
        qs[n * 33 + d] = qg[idx] * scale;
        ks[n * 33 + d] = kg[idx];
        vs[n * 33 + d] = vg[idx];
    }
    __syncthreads();

    for (int n = w; n < NTOK; n += 8) {
        float s[8];
#pragma unroll
        for (int u = 0; u < 8; u++) {
            int j = lane + 32 * u;
            float a = 0.f;
#pragma unroll 8
            for (int d = 0; d < HD; d++) a = fmaf(qs[n * 33 + d], ks[j * 33 + d], a);
            s[u] = a;
        }
        float mx = s[0];
#pragma unroll
        for (int u = 1; u < 8; u++) mx = fmaxf(mx, s[u]);
#pragma unroll
        for (int o = 16; o > 0; o >>= 1) mx = fmaxf(mx, __shfl_xor_sync(0xffffffffu, mx, o));
        float sum = 0.f;
#pragma unroll
        for (int u = 0; u < 8; u++) { s[u] = __expf(s[u] - mx); sum += s[u]; }
#pragma unroll
        for (int o = 16; o > 0; o >>= 1) sum += __shfl_xor_sync(0xffffffffu, sum, o);
        float inv = 1.f / sum;
#pragma unroll
        for (int u = 0; u < 8; u++) prob[w * 256 + lane + 32 * u] = s[u] * inv;
        __syncwarp();
        float acc = 0.f;
#pragma unroll 8
        for (int j = 0; j < NTOK; j++) acc = fmaf(prob[w * 256 + j], vs[j * 33 + lane], acc);
        g_attnout[(b * NTOK + n) * CDIM + h * HD + lane] = acc;
        __syncwarp();
    }
}

// ---------------------------------------------------------------------------
// K3: x1 = LN(x + attnout @ wo + bo; g1,b1)
// ---------------------------------------------------------------------------
__global__ void proj_ln_kernel(const float* __restrict__ x,
                               const float* __restrict__ wo,
                               const float* __restrict__ bo,
                               const float* __restrict__ g1,
                               const float* __restrict__ b1) {
    __shared__ __align__(16) float As[CDIM * 36];
    int tid = threadIdx.x, cg = tid & 31, rg = tid >> 5;
    int r0 = blockIdx.x * 32;
    for (int idx = tid; idx < 32 * CDIM; idx += 256) {
        int c = idx & 255, m = idx >> 8;
        As[c * 36 + m] = g_attnout[(r0 + m) * CDIM + c];
    }
    __syncthreads();

    float acc[4][8];
#pragma unroll
    for (int j = 0; j < 8; j++) {
        float bv = bo[cg + 32 * j];
#pragma unroll
        for (int mm = 0; mm < 4; mm++) acc[mm][j] = bv;
    }
    int m0 = rg * 4;
    const float* wp = wo + cg;
#pragma unroll 4
    for (int k = 0; k < CDIM; k++) {
        float4 av = *(const float4*)(As + k * 36 + m0);
#pragma unroll
        for (int j = 0; j < 8; j++) {
            float w = wp[k * CDIM + 32 * j];
            acc[0][j] = fmaf(av.x, w, acc[0][j]);
            acc[1][j] = fmaf(av.y, w, acc[1][j]);
            acc[2][j] = fmaf(av.z, w, acc[2][j]);
            acc[3][j] = fmaf(av.w, w, acc[3][j]);
        }
    }
#pragma unroll
    for (int mm = 0; mm < 4; mm++) {
        int r = r0 + m0 + mm;
#pragma unroll
        for (int j = 0; j < 8; j++) acc[mm][j] += x[r * CDIM + cg + 32 * j];
        float ls = 0.f, lq = 0.f;
#pragma unroll
        for (int j = 0; j < 8; j++) { ls += acc[mm][j]; lq += acc[mm][j] * acc[mm][j]; }
#pragma unroll
        for (int o = 16; o > 0; o >>= 1) {
            ls += __shfl_xor_sync(0xffffffffu, ls, o);
            lq += __shfl_xor_sync(0xffffffffu, lq, o);
        }
        float mean = ls * (1.f / 256.f);
        float var  = lq * (1.f / 256.f) - mean * mean;
        float rstd = rsqrtf(var + EPSLN);
#pragma unroll
        for (int j = 0; j < 8; j++) {
            int c = cg + 32 * j;
            g_x1[r * CDIM + c] = (acc[mm][j] - mean) * rstd * g1[c] + b1[c];
        }
    }
}

// ---------------------------------------------------------------------------
// K4: persistent ODE kernel. 128 CTAs x 256 threads; 16 rows/CTA.
// Thread tile: 8 rows x 2 cols (rows packed as 4 x f32x2).
//   cg = tid & 127 -> cols 2cg, 2cg+1 ; rg = tid >> 7 -> rows 8rg..8rg+7.
// Weights streamed through a 3-buffer cp.async ring, 2 blocks ahead.
// ---------------------------------------------------------------------------
__device__ __forceinline__ void prefetch_w(uint32_t sdst, const float* gsrc, int tid) {
#pragma unroll
    for (int i = 0; i < WBYTES / (256 * 16); i++) {   // 8 x 16B per thread
        int off = (tid + i * 256) * 16;
        cp_async16(sdst + off, (const char*)gsrc + off);
    }
    cp_commit();
}

__device__ __forceinline__ void gemm_block(uint32_t aBase, uint32_t wBase, U64 acc[2][4]) {
#pragma unroll 16
    for (int kk = 0; kk < KB; kk++) {
        U64 a0, a1, a2, a3;
        lds2x64(aBase + kk * MPB, a0, a1);
        lds2x64(aBase + kk * MPB + 16, a2, a3);
        float w0f, w1f;
        lds2f(wBase + kk * (CDIM * 4), w0f, w1f);
        U64 w0 = pack2(w0f, w0f), w1 = pack2(w1f, w1f);
        acc[0][0] = fma2(a0, w0, acc[0][0]); acc[0][1] = fma2(a1, w0, acc[0][1]);
        acc[0][2] = fma2(a2, w0, acc[0][2]); acc[0][3] = fma2(a3, w0, acc[0][3]);
        acc[1][0] = fma2(a0, w1, acc[1][0]); acc[1][1] = fma2(a1, w1, acc[1][1]);
        acc[1][2] = fma2(a2, w1, acc[1][2]); acc[1][3] = fma2(a3, w1, acc[1][3]);
    }
}

__device__ __forceinline__ void ldTile(uint32_t base, U64 t[2][4]) {
#pragma unroll
    for (int c = 0; c < 2; c++) {
        lds2x64(base + c * MPB, t[c][0], t[c][1]);
        lds2x64(base + c * MPB + 16, t[c][2], t[c][3]);
    }
}
__device__ __forceinline__ void stTile(uint32_t base, U64 t[2][4]) {
#pragma unroll
    for (int c = 0; c < 2; c++) {
        sts2x64(base + c * MPB, t[c][0], t[c][1]);
        sts2x64(base + c * MPB + 16, t[c][2], t[c][3]);
    }
}

__global__ void __launch_bounds__(256, 1)
ode_kernel(const int* __restrict__ lead_times, const int* __restrict__ nsp,
           const float* __restrict__ wl1, const float* __restrict__ bl1,
           const float* __restrict__ wl2, const float* __restrict__ bl2,
           const float* __restrict__ gn, const float* __restrict__ bn) {
    extern __shared__ __align__(16) float sm[];
    uint32_t sbase = (uint32_t)__cvta_generic_to_shared(sm);
    float* red = sm + OFF_RED / 4;   // [8 warps][8 rows] sums, +64 sqsums

    int tid = threadIdx.x;
    int cg = tid & 127, rg = tid >> 7;
    int lane = tid & 31, warp = tid >> 5;
    int r0 = blockIdx.x * MROW;
    int steps = lead_times[r0 >> 8];
    int ns = nsp ? nsp[0] : 50;
    if (steps > ns) steps = ns;
    if (steps < 0) steps = 0;

    // per-thread packed constants for the 2 owned cols
    U64 bl1p[2], bl2p[2], gnp[2], bnp[2];
#pragma unroll
    for (int c = 0; c < 2; c++) {
        float v1 = bl1[2 * cg + c], v2 = bl2[2 * cg + c];
        float vg = gn[2 * cg + c],  vb = bn[2 * cg + c];
        bl1p[c] = pack2(v1, v1); bl2p[c] = pack2(v2, v2);
        gnp[c]  = pack2(vg, vg); bnp[c]  = pack2(vb, vb);
    }
    const U64 THREE = pack2(3.f, 3.f);
    const U64 DT8   = pack2(DT * 0.125f, DT * 0.125f);
    const U64 DT3   = pack2(DT * (1.f / 3.f), DT * (1.f / 3.f));
    const U64 DTP   = pack2(DT, DT);
    const U64 M3RD  = pack2(-1.f / 3.f, -1.f / 3.f);
    const U64 NEG1  = pack2(-1.f, -1.f);

    // load x1 -> ys (transposed [c][m])
    for (int idx = tid; idx < MROW * CDIM; idx += 256) {
        int c = idx & 255, m = idx >> 8;
        sm[OFF_YS / 4 + c * MP + m] = g_x1[(r0 + m) * CDIM + c];
    }
    __syncthreads();

    const uint32_t wb[3] = { sbase + OFF_W0, sbase + OFF_W1, sbase + OFF_W2 };
    uint32_t colOff = (uint32_t)(2 * cg) * MPB + (uint32_t)rg * 32;
    uint32_t cg8 = (uint32_t)cg * 8;
    uint32_t aRow = (uint32_t)rg * 32;

    // prime the weight ring: blocks 0,1 of the 16-block feval sequence
    prefetch_w(wb[0], wl1, tid);
    prefetch_w(wb[1], wl1 + KB * CDIM, tid);
    int bph = 0;  // buffer holding current block

    for (int s = 0; s < steps; s++) {
        for (int st = 0; st < 4; st++) {
            uint32_t srcOff = (st == 0) ? (uint32_t)OFF_YS : (uint32_t)OFF_ARGS;
            U64 acc[2][4];
            acc[0][0] = bl1p[0]; acc[0][1] = bl1p[0]; acc[0][2] = bl1p[0]; acc[0][3] = bl1p[0];
            acc[1][0] = bl1p[1]; acc[1][1] = bl1p[1]; acc[1][2] = bl1p[1]; acc[1][3] = bl1p[1];

            for (int p = 0; p < 16; p++) {
                cp_wait1();
                __syncthreads();
                // prefetch block p+2 (mod 16; sequence is periodic across fevals)
                int nb = (p + 2) & 15;
                const float* gsrc = (nb < 8) ? (wl1 + nb * (KB * CDIM))
                                             : (wl2 + (nb - 8) * (KB * CDIM));
                int bnext = bph + 2; if (bnext >= 3) bnext -= 3;
                prefetch_w(wb[bnext], gsrc, tid);
                // compute block p
                uint32_t aB = sbase + ((p < 8) ? srcOff : (uint32_t)OFF_H1)
                            + (uint32_t)(p & 7) * (KB * MPB) + aRow;
                gemm_block(aB, wb[bph] + cg8, acc);
                bph = bph + 1; if (bph == 3) bph = 0;

                if (p == 7) {
                    // relu -> h1, then switch to GEMM2 accumulators
#pragma unroll
                    for (int c = 0; c < 2; c++) {
                        float f0, f1, f2, f3, f4, f5, f6, f7;
                        unpack2(acc[c][0], f0, f1); unpack2(acc[c][1], f2, f3);
                        unpack2(acc[c][2], f4, f5); unpack2(acc[c][3], f6, f7);
                        uint32_t hB = sbase + OFF_H1 + colOff + c * MPB;
                        sts4f(hB,      fmaxf(f0, 0.f), fmaxf(f1, 0.f), fmaxf(f2, 0.f), fmaxf(f3, 0.f));
                        sts4f(hB + 16, fmaxf(f4, 0.f), fmaxf(f5, 0.f), fmaxf(f6, 0.f), fmaxf(f7, 0.f));
                    }
                    acc[0][0] = bl2p[0]; acc[0][1] = bl2p[0]; acc[0][2] = bl2p[0]; acc[0][3] = bl2p[0];
                    acc[1][0] = bl2p[1]; acc[1][1] = bl2p[1]; acc[1][2] = bl2p[1]; acc[1][3] = bl2p[1];
                }
            }

            // ---- epilogue: residual + LN + k-store + arg build (fused) ----
            U64 rs[2][4];
            ldTile(sbase + srcOff + colOff, rs);
#pragma unroll
            for (int c = 0; c < 2; c++)
#pragma unroll
                for (int j = 0; j < 4; j++) acc[c][j] = add2(acc[c][j], rs[c][j]);

            float sv[8], qv[8];
#pragma unroll
            for (int j = 0; j < 4; j++) {
                U64 S = add2(acc[0][j], acc[1][j]);
                U64 Q = fma2(acc[1][j], acc[1][j], mul2(acc[0][j], acc[0][j]));
                unpack2(S, sv[2 * j], sv[2 * j + 1]);
                unpack2(Q, qv[2 * j], qv[2 * j + 1]);
            }
#pragma unroll
            for (int o = 16; o > 0; o >>= 1) {
#pragma unroll
                for (int r = 0; r < 8; r++) {
                    sv[r] += __shfl_xor_sync(0xffffffffu, sv[r], o);
                    qv[r] += __shfl_xor_sync(0xffffffffu, qv[r], o);
                }
            }
            if (lane == 0) {
#pragma unroll
                for (int r = 0; r < 8; r++) {
                    red[warp * 8 + r] = sv[r];
                    red[64 + warp * 8 + r] = qv[r];
                }
            }
            __syncthreads();
            float Af[8], Bf[8];
#pragma unroll
            for (int r = 0; r < 8; r++) {
                int base = (rg * 4) * 8 + r;
                float ts = red[base] + red[base + 8] + red[base + 16] + red[base + 24];
                float tq = red[64 + base] + red[64 + base + 8] + red[64 + base + 16] + red[64 + base + 24];
                float mean = ts * (1.f / 256.f);
                float var  = tq * (1.f / 256.f) - mean * mean;
                float rstd = rsqrtf(var + EPSLN);
                Af[r] = rstd; Bf[r] = -mean * rstd;
            }
            U64 Ap[4], Bp[4];
#pragma unroll
            for (int j = 0; j < 4; j++) {
                Ap[j] = pack2(Af[2 * j], Af[2 * j + 1]);
                Bp[j] = pack2(Bf[2 * j], Bf[2 * j + 1]);
            }
            U64 kv[2][4];
#pragma unroll
            for (int c = 0; c < 2; c++)
#pragma unroll
                for (int j = 0; j < 4; j++)
                    kv[c][j] = fma2(fma2(acc[c][j], Ap[j], Bp[j]), gnp[c], bnp[c]);

            if (st == 0) {
                // rs == y here. k1 = kv; arg = y + dt/3 * k1
                stTile(sbase + OFF_K1 + colOff, kv);
                U64 ar[2][4];
#pragma unroll
                for (int c = 0; c < 2; c++)
#pragma unroll
                    for (int j = 0; j < 4; j++) ar[c][j] = fma2(kv[c][j], DT3, rs[c][j]);
                stTile(sbase + OFF_ARGS + colOff, ar);
            } else if (st == 1) {
                U64 yv[2][4], k1[2][4];
                ldTile(sbase + OFF_YS + colOff, yv);
                ldTile(sbase + OFF_K1 + colOff, k1);
                stTile(sbase + OFF_K2 + colOff, kv);
                U64 ar[2][4];
#pragma unroll
                for (int c = 0; c < 2; c++)
#pragma unroll
                    for (int j = 0; j < 4; j++) {
                        U64 t = fma2(k1[c][j], M3RD, kv[c][j]);      // k2 - k1/3
                        ar[c][j] = fma2(t, DTP, yv[c][j]);
                    }
                stTile(sbase + OFF_ARGS + colOff, ar);
            } else if (st == 2) {
                U64 yv[2][4], k1[2][4], k2[2][4];
                ldTile(sbase + OFF_YS + colOff, yv);
                ldTile(sbase + OFF_K1 + colOff, k1);
                ldTile(sbase + OFF_K2 + colOff, k2);
                stTile(sbase + OFF_K3 + colOff, kv);
                U64 ar[2][4];
#pragma unroll
                for (int c = 0; c < 2; c++)
#pragma unroll
                    for (int j = 0; j < 4; j++) {
                        U64 t = add2(fma2(k2[c][j], NEG1, k1[c][j]), kv[c][j]); // k1-k2+k3
                        ar[c][j] = fma2(t, DTP, yv[c][j]);
                    }
                stTile(sbase + OFF_ARGS + colOff, ar);
            } else {
                U64 yv[2][4], k1[2][4], k2[2][4], k3[2][4];
                ldTile(sbase + OFF_YS + colOff, yv);
                ldTile(sbase + OFF_K1 + colOff, k1);
                ldTile(sbase + OFF_K2 + colOff, k2);
                ldTile(sbase + OFF_K3 + colOff, k3);
#pragma unroll
                for (int c = 0; c < 2; c++)
#pragma unroll
                    for (int j = 0; j < 4; j++) {
                        U64 t = fma2(add2(k2[c][j], k3[c][j]), THREE, k1[c][j]);
                        t = add2(t, kv[c][j]);
                        yv[c][j] = fma2(t, DT8, yv[c][j]);
                    }
                stTile(sbase + OFF_YS + colOff, yv);
            }
            // next feval's first block sync publishes these stores
        }
    }

    cp_wait_all();
    __syncthreads();
    for (int idx = tid; idx < MROW * CDIM; idx += 256) {
        int c = idx & 255, m = idx >> 8;
        g_ode[(r0 + m) * CDIM + c] = sm[OFF_YS / 4 + c * MP + m];
    }
}

// ---------------------------------------------------------------------------
// K5: out = LN(x1 + ode; g2,b2)
// ---------------------------------------------------------------------------
__global__ void final_ln_kernel(const float* __restrict__ g2,
                                const float* __restrict__ b2,
                                float* __restrict__ out) {
    int tid = threadIdx.x, lane = tid & 31, w = tid >> 5;
    int r = blockIdx.x * 8 + w;
    float v[8], ls = 0.f, lq = 0.f;
#pragma unroll
    for (int u = 0; u < 8; u++) {
        int c = lane + 32 * u;
        float t = g_x1[r * CDIM + c] + g_ode[r * CDIM + c];
        v[u] = t; ls += t; lq += t * t;
    }
#pragma unroll
    for (int o = 16; o > 0; o >>= 1) {
        ls += __shfl_xor_sync(0xffffffffu, ls, o);
        lq += __shfl_xor_sync(0xffffffffu, lq, o);
    }
    float mean = ls * (1.f / 256.f);
    float var  = lq * (1.f / 256.f) - mean * mean;
    float rstd = rsqrtf(var + EPSLN);
#pragma unroll
    for (int u = 0; u < 8; u++) {
        int c = lane + 32 * u;
        out[r * CDIM + c] = (v[u] - mean) * rstd * g2[c] + b2[c];
    }
}

// ---------------------------------------------------------------------------
// Launch
// ---------------------------------------------------------------------------
extern "C" void kernel_launch(void* const* d_in, const int* in_sizes, int n_in,
                              void* d_out, int out_size) {
    const float* x    = (const float*)d_in[0];
    const float* wqkv = (const float*)d_in[1];
    const float* bqkv = (const float*)d_in[2];
    const float* wo   = (const float*)d_in[3];
    const float* bo   = (const float*)d_in[4];
    const float* g1   = (const float*)d_in[5];
    const float* b1   = (const float*)d_in[6];
    const float* g2   = (const float*)d_in[7];
    const float* b2   = (const float*)d_in[8];
    const float* wl1  = (const float*)d_in[9];
    const float* bl1  = (const float*)d_in[10];
    const float* wl2  = (const float*)d_in[11];
    const float* bl2  = (const float*)d_in[12];
    const float* gn   = (const float*)d_in[13];
    const float* bn   = (const float*)d_in[14];
    const int* lead   = (const int*)d_in[15];
    const int* nsteps = (n_in > 16) ? (const int*)d_in[16] : nullptr;
    float* out = (float*)d_out;

    cudaFuncSetAttribute(attn_kernel, cudaFuncAttributeMaxDynamicSharedMemorySize, ATTN_SMEM);
    cudaFuncSetAttribute(ode_kernel, cudaFuncAttributeMaxDynamicSharedMemorySize, ODE_SMEM);

    qkv_kernel<<<dim3(64, 3), 256>>>(x, wqkv, bqkv);
    attn_kernel<<<64, 256, ATTN_SMEM>>>();
    proj_ln_kernel<<<64, 256>>>(x, wo, bo, g1, b1);
    ode_kernel<<<128, 256, ODE_SMEM>>>(lead, nsteps, wl1, bl1, wl2, bl2, gn, bn);
    final_ln_kernel<<<256, 256>>>(g2, b2, out);
}